// round 1
// baseline (speedup 1.0000x reference)
#include <cuda_runtime.h>
#include <cstdint>

// Problem constants
#define N_TOK   8192
#define S_CH    32
#define D_DIM   32
#define K_CODE  1024
#define IN_DIM  1024

#define ROWS_PER_CTA 64
#define THREADS_MAIN 128
#define NCTA_X (N_TOK / ROWS_PER_CTA)   // 128
#define NPART  (NCTA_X * S_CH)          // 4096

// Device scratch (no allocations allowed in kernel_launch)
__device__ float g_wsq[S_CH * K_CODE];
__device__ float g_partial[NPART];

// ---------------------------------------------------------------------------
// Kernel 1: wsq[s][k] = sum_d W[s][k][d]^2
// ---------------------------------------------------------------------------
__global__ void wsq_kernel(const float* __restrict__ W) {
    int i = blockIdx.x * blockDim.x + threadIdx.x; // 0..32767
    if (i >= S_CH * K_CODE) return;
    const float4* w4 = reinterpret_cast<const float4*>(W + (size_t)i * D_DIM);
    float s = 0.f;
#pragma unroll
    for (int j = 0; j < 8; j++) {
        float4 v = __ldg(&w4[j]);
        s += v.x * v.x + v.y * v.y + v.z * v.z + v.w * v.w;
    }
    g_wsq[i] = s;
}

// ---------------------------------------------------------------------------
// Kernel 2: main VQ kernel.
// CTA = (64 n-rows, one chunk s). 4 warps each own a 256-wide k range.
// Each lane owns 2 rows (z in registers). Codeword broadcast via __ldg (L2).
// ---------------------------------------------------------------------------
__global__ __launch_bounds__(THREADS_MAIN, 4)
void vq_kernel(const float* __restrict__ z,
               const float* __restrict__ W,
               float* __restrict__ out)
{
    __shared__ float s_zT[D_DIM][ROWS_PER_CTA];   // transposed z tile: 8KB
    __shared__ float s_wsq[K_CODE];               // 4KB
    __shared__ float s_best[4][ROWS_PER_CTA];
    __shared__ int   s_bidx[4][ROWS_PER_CTA];
    __shared__ float s_loss[ROWS_PER_CTA];

    const int s  = blockIdx.y;
    const int n0 = blockIdx.x * ROWS_PER_CTA;
    const int tid = threadIdx.x;

    // ---- load z tile (transposed into smem) + wsq row ----
    {
        const float4* zg = reinterpret_cast<const float4*>(z);
        // 64 rows * 8 float4 = 512 vector loads, coalesced 128B per 8 threads
        for (int i = tid; i < ROWS_PER_CTA * 8; i += THREADS_MAIN) {
            int r = i >> 3, c = i & 7;
            float4 v = zg[(size_t)(n0 + r) * (IN_DIM / 4) + s * 8 + c];
            s_zT[c * 4 + 0][r] = v.x;
            s_zT[c * 4 + 1][r] = v.y;
            s_zT[c * 4 + 2][r] = v.z;
            s_zT[c * 4 + 3][r] = v.w;
        }
        for (int i = tid; i < K_CODE; i += THREADS_MAIN)
            s_wsq[i] = g_wsq[s * K_CODE + i];
    }
    __syncthreads();

    const int warp = tid >> 5;
    const int lane = tid & 31;
    const int r0 = lane * 2;

    // copy the 2 owned rows to registers (conflict-free float2 LDS)
    float zr0[D_DIM], zr1[D_DIM];
#pragma unroll
    for (int d = 0; d < D_DIM; d++) {
        float2 v = *reinterpret_cast<const float2*>(&s_zT[d][r0]);
        zr0[d] = v.x; zr1[d] = v.y;
    }
    float zsq0 = 0.f, zsq1 = 0.f;
#pragma unroll
    for (int d = 0; d < D_DIM; d++) {
        zsq0 = fmaf(zr0[d], zr0[d], zsq0);
        zsq1 = fmaf(zr1[d], zr1[d], zsq1);
    }

    float best0 = 3.4e38f, best1 = 3.4e38f;
    int   bi0 = 0, bi1 = 0;

    const int kbase = warp * (K_CODE / 4);
    const float4* Wb = reinterpret_cast<const float4*>(
        W + ((size_t)s * K_CODE + kbase) * D_DIM);

#pragma unroll 2
    for (int kk = 0; kk < K_CODE / 4; kk++) {
        const int k = kbase + kk;
        float4 w0 = __ldg(&Wb[kk * 8 + 0]);
        float4 w1 = __ldg(&Wb[kk * 8 + 1]);
        float4 w2 = __ldg(&Wb[kk * 8 + 2]);
        float4 w3 = __ldg(&Wb[kk * 8 + 3]);
        float4 w4 = __ldg(&Wb[kk * 8 + 4]);
        float4 w5 = __ldg(&Wb[kk * 8 + 5]);
        float4 w6 = __ldg(&Wb[kk * 8 + 6]);
        float4 w7 = __ldg(&Wb[kk * 8 + 7]);

        float wv[D_DIM];
        wv[0]=w0.x; wv[1]=w0.y; wv[2]=w0.z; wv[3]=w0.w;
        wv[4]=w1.x; wv[5]=w1.y; wv[6]=w1.z; wv[7]=w1.w;
        wv[8]=w2.x; wv[9]=w2.y; wv[10]=w2.z; wv[11]=w2.w;
        wv[12]=w3.x; wv[13]=w3.y; wv[14]=w3.z; wv[15]=w3.w;
        wv[16]=w4.x; wv[17]=w4.y; wv[18]=w4.z; wv[19]=w4.w;
        wv[20]=w5.x; wv[21]=w5.y; wv[22]=w5.z; wv[23]=w5.w;
        wv[24]=w6.x; wv[25]=w6.y; wv[26]=w6.z; wv[27]=w6.w;
        wv[28]=w7.x; wv[29]=w7.y; wv[30]=w7.z; wv[31]=w7.w;

        float dot0 = 0.f, dot1 = 0.f;
#pragma unroll
        for (int d = 0; d < D_DIM; d++) {
            dot0 = fmaf(zr0[d], wv[d], dot0);
            dot1 = fmaf(zr1[d], wv[d], dot1);
        }
        // Match reference formula order: (zsq + wsq) - 2*dot
        float wk  = s_wsq[k];
        float d20 = (zsq0 + wk) - 2.0f * dot0;
        float d21 = (zsq1 + wk) - 2.0f * dot1;
        if (d20 < best0) { best0 = d20; bi0 = k; }   // strict <: first-min tie-break
        if (d21 < best1) { best1 = d21; bi1 = k; }
    }

    s_best[warp][r0]     = best0;  s_bidx[warp][r0]     = bi0;
    s_best[warp][r0 + 1] = best1;  s_bidx[warp][r0 + 1] = bi1;
    __syncthreads();

    // ---- per-row final reduce (ascending split order = ascending k), gather,
    //      output write, exact loss contribution ----
    if (tid < ROWS_PER_CTA) {
        const int r = tid;
        float b = s_best[0][r];
        int  bi = s_bidx[0][r];
#pragma unroll
        for (int w = 1; w < 4; w++) {
            float cb = s_best[w][r];
            int   ci = s_bidx[w][r];
            if (cb < b) { b = cb; bi = ci; }
        }
        const float4* wrow = reinterpret_cast<const float4*>(
            W + ((size_t)s * K_CODE + bi) * D_DIM);
        float4* orow = reinterpret_cast<float4*>(
            out + (size_t)(n0 + r) * IN_DIM + s * D_DIM);
        float ls = 0.f;
#pragma unroll
        for (int j = 0; j < 8; j++) {
            float4 v = __ldg(&wrow[j]);
            float a0 = v.x - s_zT[j * 4 + 0][r];
            float a1 = v.y - s_zT[j * 4 + 1][r];
            float a2 = v.z - s_zT[j * 4 + 2][r];
            float a3 = v.w - s_zT[j * 4 + 3][r];
            ls = fmaf(a0, a0, ls);
            ls = fmaf(a1, a1, ls);
            ls = fmaf(a2, a2, ls);
            ls = fmaf(a3, a3, ls);
            orow[j] = v;
        }
        s_loss[r] = ls;
    }
    __syncthreads();

    // deterministic fixed-order CTA partial sum
    if (tid == 0) {
        float acc = 0.f;
#pragma unroll
        for (int r = 0; r < ROWS_PER_CTA; r++) acc += s_loss[r];
        g_partial[blockIdx.y * gridDim.x + blockIdx.x] = acc;
    }
}

// ---------------------------------------------------------------------------
// Kernel 3: deterministic reduction of partials -> scalar loss
// ---------------------------------------------------------------------------
__global__ void finalize_kernel(float* __restrict__ out, int out_size) {
    __shared__ float sm[256];
    float a = 0.f;
    for (int i = threadIdx.x; i < NPART; i += 256) a += g_partial[i];
    sm[threadIdx.x] = a;
    __syncthreads();
#pragma unroll
    for (int off = 128; off > 0; off >>= 1) {
        if (threadIdx.x < off) sm[threadIdx.x] += sm[threadIdx.x + off];
        __syncthreads();
    }
    if (threadIdx.x == 0) {
        float m = sm[0] / (float)((size_t)N_TOK * S_CH * D_DIM); // / 8388608
        float loss = (float)S_CH * (m + 0.001f * m);             // S*(mean + BETA*mean)
        if (out_size > N_TOK * IN_DIM) out[out_size - 1] = loss;
    }
}

// ---------------------------------------------------------------------------
extern "C" void kernel_launch(void* const* d_in, const int* in_sizes, int n_in,
                              void* d_out, int out_size) {
    const float* z = (const float*)d_in[0];   // (8192, 1024) f32
    const float* W = (const float*)d_in[1];   // (32, 1024, 32) f32
    float* out = (float*)d_out;

    wsq_kernel<<<(S_CH * K_CODE + 127) / 128, 128>>>(W);

    dim3 grid(NCTA_X, S_CH);
    vq_kernel<<<grid, THREADS_MAIN>>>(z, W, out);

    finalize_kernel<<<1, 256>>>(out, out_size);
}